// round 6
// baseline (speedup 1.0000x reference)
#include <cuda_runtime.h>
#include <cuda_bf16.h>
#include <cstdint>

// ---------------- fixed shapes ----------------
constexpr int H_ = 16, NQ_ = 2048, NKV_ = 4096, D_ = 128, PD_ = 64;
constexpr float SC2 = 0.18033688011112042f;  // 0.125 * log2(e)

// ---------------- packed fragment buffers (gmem scratch, no cudaMalloc) ----
// Qpk: [h][strip(128)][s(4)][lane(32)][8 u32]  (0-3 hi a0..a3, 4-7 lo)
__device__ __align__(16) uint32_t g_Qpk[H_ * 128 * 4 * 32 * 8];    // 8 MB
// Kpk: [h][j(512)][s(4)][lane(32)][4 u32]  {bh0,bh1,bl0,bl1}
__device__ __align__(16) uint32_t g_Kpk[H_ * 512 * 4 * 32 * 4];    // 16 MB
// Vpk: [h][tk(256)][j(16)][lane(32)][4 u32]  {vh0,vh1,vl0,vl1}
__device__ __align__(16) uint32_t g_Vpk[H_ * 256 * 16 * 32 * 4];   // 32 MB

// ---------------- helpers ----------------
__device__ __forceinline__ uint32_t s2u(const void* p) {
    uint32_t a;
    asm("{ .reg .u64 t; cvta.to.shared.u64 t, %1; cvt.u32.u64 %0, t; }" : "=r"(a) : "l"(p));
    return a;
}
__device__ __forceinline__ float fex2(float x) {
    float y; asm("ex2.approx.ftz.f32 %0, %1;" : "=f"(y) : "f"(x)); return y;
}
__device__ __forceinline__ uint32_t pk(__nv_bfloat16 a, __nv_bfloat16 b) {
    __nv_bfloat162 t = __halves2bfloat162(a, b);  // a -> low 16
    return *reinterpret_cast<uint32_t*>(&t);
}
__device__ __forceinline__ uint32_t pk_hi(float a, float b) {
    return pk(__float2bfloat16(a), __float2bfloat16(b));
}
__device__ __forceinline__ uint32_t pk_lo(float a, float b) {
    const __nv_bfloat16 ha = __float2bfloat16(a), hb = __float2bfloat16(b);
    return pk(__float2bfloat16(a - __bfloat162float(ha)),
              __float2bfloat16(b - __bfloat162float(hb)));
}
__device__ __forceinline__ void split(float v, __nv_bfloat16& h, __nv_bfloat16& l) {
    h = __float2bfloat16(v);
    l = __float2bfloat16(v - __bfloat162float(h));
}
__device__ __forceinline__ void mma_bf16(float* c, const uint32_t* a,
                                         uint32_t b0, uint32_t b1) {
    asm volatile("mma.sync.aligned.m16n8k16.row.col.f32.bf16.bf16.f32 "
        "{%0,%1,%2,%3}, {%4,%5,%6,%7}, {%8,%9}, {%0,%1,%2,%3};"
        : "+f"(c[0]), "+f"(c[1]), "+f"(c[2]), "+f"(c[3])
        : "r"(a[0]), "r"(a[1]), "r"(a[2]), "r"(a[3]), "r"(b0), "r"(b1));
}
#define CP16(d, s) asm volatile("cp.async.cg.shared.global [%0], [%1], 16;" \
                                :: "r"(d), "l"(s) : "memory")
#define CP_COMMIT() asm volatile("cp.async.commit_group;" ::: "memory")
#define CP_WAIT(n)  asm volatile("cp.async.wait_group %0;" :: "n"(n) : "memory")

// ---------------- prep: projection + split + pack (coalesced stores) ------
struct ProjSmem {
    float Rs[128 * 64];      // 32 KB
    float rowbuf[32 * 128];  // 16 KB
    float proj[32][65];      // 8.3 KB staged outputs
};
constexpr int PROJ_SMEM = sizeof(ProjSmem);

template <int ISQ>
__global__ void __launch_bounds__(256) proj_pack(
    const float* __restrict__ in, const float* __restrict__ R,
    uint32_t* __restrict__ outpk)
{
    extern __shared__ char sraw[];
    ProjSmem& sm = *reinterpret_cast<ProjSmem*>(sraw);
    const int tid = threadIdx.x, row0 = blockIdx.x * 32;
    #pragma unroll
    for (int i = 0; i < 32; i++) sm.Rs[tid + 256 * i] = R[tid + 256 * i];
    #pragma unroll
    for (int i = 0; i < 16; i++)
        sm.rowbuf[tid + 256 * i] = in[(size_t)row0 * 128 + tid + 256 * i];
    __syncthreads();

    const int p = tid & 63, rsub = tid >> 6;
    float acc[8];
    #pragma unroll
    for (int i = 0; i < 8; i++) acc[i] = 0.f;
    #pragma unroll 4
    for (int d = 0; d < 128; d++) {
        const float rv = sm.Rs[d * 64 + p];
        #pragma unroll
        for (int it = 0; it < 8; it++)
            acc[it] += sm.rowbuf[(rsub + 4 * it) * 128 + d] * rv;
    }
    #pragma unroll
    for (int it = 0; it < 8; it++) sm.proj[rsub + 4 * it][p] = acc[it];
    __syncthreads();

    if (ISQ) {
        const int h = row0 >> 11, strip0 = (row0 & 2047) >> 4;
        #pragma unroll
        for (int i = 0; i < 8; i++) {
            const int w = tid + 256 * i;
            const int strip_l = w >> 10, s = (w >> 8) & 3;
            const int lane = (w >> 3) & 31, widx = w & 7;
            const int wr = widx & 3, lohi = widx >> 2;
            const int row_l = strip_l * 16 + (wr & 1) * 8 + (lane >> 2);
            const int p0 = s * 16 + ((wr >> 1) & 1) * 8 + (lane & 3) * 2;
            const float a = sm.proj[row_l][p0], b = sm.proj[row_l][p0 + 1];
            const uint32_t word = lohi ? pk_lo(a, b) : pk_hi(a, b);
            outpk[((((size_t)h * 128 + strip0 + strip_l) * 4 + s) * 32 + lane) * 8 + widx] = word;
        }
    } else {
        const int h = row0 >> 12, j0 = (row0 & 4095) >> 3;
        #pragma unroll
        for (int i = 0; i < 8; i++) {
            const int w = tid + 256 * i;
            const int jj = w >> 9, s = (w >> 7) & 3;
            const int lane = (w >> 2) & 31, widx = w & 3;
            const int lohi = widx >> 1, hw = widx & 1;
            const int row_l = jj * 8 + (lane >> 2);
            const int p0 = s * 16 + hw * 8 + (lane & 3) * 2;
            const float a = sm.proj[row_l][p0], b = sm.proj[row_l][p0 + 1];
            const uint32_t word = lohi ? pk_lo(a, b) : pk_hi(a, b);
            outpk[((((size_t)h * 512 + j0 + jj) * 4 + s) * 32 + lane) * 4 + widx] = word;
        }
    }
}

// ---------------- prep: V split + pack (coalesced) ----------------
__global__ void __launch_bounds__(256) vpack(
    const float* __restrict__ V, uint32_t* __restrict__ outpk)
{
    __shared__ float vt[16][129];
    const int tid = threadIdx.x;
    const int h = blockIdx.x >> 8, tk = blockIdx.x & 255;
    const float* src = V + ((size_t)h * NKV_ + tk * 16) * D_;
    #pragma unroll
    for (int i = 0; i < 8; i++) {
        const int idx = tid + 256 * i;
        vt[idx >> 7][idx & 127] = src[idx];
    }
    __syncthreads();
    #pragma unroll
    for (int i = 0; i < 8; i++) {
        const int w = tid + 256 * i;
        const int j = w >> 7, lane = (w >> 2) & 31, widx = w & 3;
        const int hw = widx & 1, lohi = widx >> 1;
        const int kv0 = hw * 8 + (lane & 3) * 2, d = j * 8 + (lane >> 2);
        const float a = vt[kv0][d], b = vt[kv0 + 1][d];
        const uint32_t word = lohi ? pk_lo(a, b) : pk_hi(a, b);
        outpk[((((size_t)h * 256 + tk) * 16 + j) * 32 + lane) * 4 + widx] = word;
    }
}

// ---------------- flash attention: 128-thr CTAs, kv-tile 64, 2 CTAs/SM ----
constexpr int KT_U32 = 8 * 4 * 32 * 4;         // 16 KB (8 j per tile)
constexpr int VT_U32 = 4 * 16 * 32 * 4;        // 32 KB (4 tk per tile)
constexpr int BUF_U32 = KT_U32 + VT_U32;       // 12288 u32 = 48 KB
constexpr int FLASH_SMEM = 2 * BUF_U32 * 4;    // 98304 B -> 2 CTAs/SM
constexpr int NT = NKV_ / 64;                  // 64 kv tiles

__device__ __forceinline__ void issue_tile(uint32_t* smem, int t, int h, int tid,
                                           const uint32_t* __restrict__ Kpk,
                                           const uint32_t* __restrict__ Vpk) {
    uint32_t* dst = smem + (t & 1) * BUF_U32;
    const uint32_t* ksrc = Kpk + ((size_t)h * 512 + (size_t)t * 8) * 512;
    const uint32_t* vsrc = Vpk + ((size_t)h * 256 + (size_t)t * 4) * 2048;
    const uint32_t ka = s2u(dst), va = s2u(dst + KT_U32);
    #pragma unroll
    for (int i = 0; i < 8; i++) {
        const int idx = tid + 128 * i;
        CP16(ka + idx * 16, ksrc + idx * 4);
    }
    #pragma unroll
    for (int i = 0; i < 16; i++) {
        const int idx = tid + 128 * i;
        CP16(va + idx * 16, vsrc + idx * 4);
    }
    CP_COMMIT();
}

__global__ void __launch_bounds__(128) flash_mma(
    const uint32_t* __restrict__ Qpk, const uint32_t* __restrict__ Kpk,
    const uint32_t* __restrict__ Vpk, float* __restrict__ Og)
{
    extern __shared__ uint32_t smem[];
    const int tid = threadIdx.x, w = tid >> 5, lane = tid & 31;
    const int gid = lane >> 2, tig = lane & 3;
    const int h = blockIdx.y, q0 = blockIdx.x * 64;
    const int strip = (q0 >> 4) + w;

    uint32_t qh[4][4], ql[4][4];
    #pragma unroll
    for (int s = 0; s < 4; s++) {
        const uint32_t* qp = Qpk + ((((size_t)h * 128 + strip) * 4 + s) * 32 + lane) * 8;
        const uint4 a = *(const uint4*)qp;
        const uint4 b = *(const uint4*)(qp + 4);
        qh[s][0] = a.x; qh[s][1] = a.y; qh[s][2] = a.z; qh[s][3] = a.w;
        ql[s][0] = b.x; ql[s][1] = b.y; ql[s][2] = b.z; ql[s][3] = b.w;
    }

    float o[16][4];
    #pragma unroll
    for (int j = 0; j < 16; j++)
        #pragma unroll
        for (int r = 0; r < 4; r++) o[j][r] = 0.f;
    float lsum0 = 0.f, lsum1 = 0.f;

    issue_tile(smem, 0, h, tid, Kpk, Vpk);

    #pragma unroll 1
    for (int t = 0; t < NT; t++) {
        if (t < NT - 1) {
            issue_tile(smem, t + 1, h, tid, Kpk, Vpk);
            CP_WAIT(1);
        } else {
            CP_WAIT(0);
        }
        __syncthreads();
        const uint32_t* kb = smem + (t & 1) * BUF_U32;
        const uint32_t* vb = kb + KT_U32;

        #pragma unroll
        for (int tk = 0; tk < 4; tk++) {
            // ---- S for j-pair (2tk, 2tk+1), exp -> P fragments ----
            uint32_t ph[4], pl[4];
            #pragma unroll
            for (int jj = 0; jj < 2; jj++) {
                const int j = tk * 2 + jj;
                float cA[4] = {0.f, 0.f, 0.f, 0.f};
                float cB[4] = {0.f, 0.f, 0.f, 0.f};
                {
                    const uint4 f0 = *(const uint4*)&kb[((j * 4 + 0) * 32 + lane) * 4];
                    mma_bf16(cA, qh[0], f0.x, f0.y);
                    mma_bf16(cA, ql[0], f0.x, f0.y);
                    mma_bf16(cA, qh[0], f0.z, f0.w);
                    const uint4 f1 = *(const uint4*)&kb[((j * 4 + 1) * 32 + lane) * 4];
                    mma_bf16(cB, qh[1], f1.x, f1.y);
                    mma_bf16(cB, ql[1], f1.x, f1.y);
                    mma_bf16(cB, qh[1], f1.z, f1.w);
                    const uint4 f2 = *(const uint4*)&kb[((j * 4 + 2) * 32 + lane) * 4];
                    mma_bf16(cA, qh[2], f2.x, f2.y);
                    mma_bf16(cA, ql[2], f2.x, f2.y);
                    mma_bf16(cA, qh[2], f2.z, f2.w);
                    const uint4 f3 = *(const uint4*)&kb[((j * 4 + 3) * 32 + lane) * 4];
                    mma_bf16(cB, qh[3], f3.x, f3.y);
                    mma_bf16(cB, ql[3], f3.x, f3.y);
                    mma_bf16(cB, qh[3], f3.z, f3.w);
                }
                const float e0 = fex2((cA[0] + cB[0]) * SC2);
                const float e1 = fex2((cA[1] + cB[1]) * SC2);
                const float e2 = fex2((cA[2] + cB[2]) * SC2);
                const float e3 = fex2((cA[3] + cB[3]) * SC2);
                lsum0 += e0 + e1;
                lsum1 += e2 + e3;
                __nv_bfloat16 h0, l0, h1, l1, h2, l2, h3, l3;
                split(e0, h0, l0); split(e1, h1, l1);
                split(e2, h2, l2); split(e3, h3, l3);
                ph[jj * 2] = pk(h0, h1); ph[jj * 2 + 1] = pk(h2, h3);
                pl[jj * 2] = pk(l0, l1); pl[jj * 2 + 1] = pk(l2, l3);
            }
            // ---- O += P(:, tk-chunk) @ V(tk-chunk, :) ----
            #pragma unroll
            for (int j = 0; j < 16; j++) {
                const uint4 f = *(const uint4*)&vb[((tk * 16 + j) * 32 + lane) * 4];
                mma_bf16(o[j], ph, f.x, f.y);   // Ph * Vh
                mma_bf16(o[j], pl, f.x, f.y);   // Pl * Vh
                mma_bf16(o[j], ph, f.z, f.w);   // Ph * Vl
            }
        }
        __syncthreads();
    }

    // ---- epilogue ----
    lsum0 += __shfl_xor_sync(0xffffffffu, lsum0, 1);
    lsum0 += __shfl_xor_sync(0xffffffffu, lsum0, 2);
    lsum1 += __shfl_xor_sync(0xffffffffu, lsum1, 1);
    lsum1 += __shfl_xor_sync(0xffffffffu, lsum1, 2);
    const float inv0 = 1.0f / lsum0, inv1 = 1.0f / lsum1;

    const int row0 = h * NQ_ + q0 + w * 16 + gid;
    #pragma unroll
    for (int j = 0; j < 16; j++) {
        const float2 v0 = make_float2(o[j][0] * inv0, o[j][1] * inv0);
        const float2 v1 = make_float2(o[j][2] * inv1, o[j][3] * inv1);
        *(float2*)(Og + (size_t)row0 * 128 + j * 8 + tig * 2) = v0;
        *(float2*)(Og + (size_t)(row0 + 8) * 128 + j * 8 + tig * 2) = v1;
    }
}

// ---------------- launch ----------------
extern "C" void kernel_launch(void* const* d_in, const int* in_sizes, int n_in,
                              void* d_out, int out_size)
{
    const float* Q = (const float*)d_in[0];
    const float* K = (const float*)d_in[1];
    const float* V = (const float*)d_in[2];
    const float* R = (const float*)d_in[3];
    float* O = (float*)d_out;

    uint32_t *qpk, *kpk, *vpk;
    cudaGetSymbolAddress((void**)&qpk, g_Qpk);
    cudaGetSymbolAddress((void**)&kpk, g_Kpk);
    cudaGetSymbolAddress((void**)&vpk, g_Vpk);

    cudaFuncSetAttribute(proj_pack<1>, cudaFuncAttributeMaxDynamicSharedMemorySize, PROJ_SMEM);
    cudaFuncSetAttribute(proj_pack<0>, cudaFuncAttributeMaxDynamicSharedMemorySize, PROJ_SMEM);
    cudaFuncSetAttribute(flash_mma, cudaFuncAttributeMaxDynamicSharedMemorySize, FLASH_SMEM);

    proj_pack<1><<<(H_ * NQ_) / 32, 256, PROJ_SMEM>>>(Q, R, qpk);
    proj_pack<0><<<(H_ * NKV_) / 32, 256, PROJ_SMEM>>>(K, R, kpk);
    vpack<<<H_ * 256, 256>>>(V, vpk);
    flash_mma<<<dim3(NQ_ / 64, H_), 128, FLASH_SMEM>>>(qpk, kpk, vpk, O);
}

// round 7
// speedup vs baseline: 1.4212x; 1.4212x over previous
#include <cuda_runtime.h>
#include <cuda_bf16.h>
#include <cstdint>

// ---------------- fixed shapes ----------------
constexpr int H_ = 16, NQ_ = 2048, NKV_ = 4096, D_ = 128, PD_ = 64;
constexpr float SC2 = 0.18033688011112042f;  // 0.125 * log2(e)

// ---------------- packed fragment buffers (gmem scratch, no cudaMalloc) ----
// Qpk: [h][strip(128)][s(4)][lane(32)][8 u32]  (0-3 hi a0..a3, 4-7 lo)
__device__ __align__(16) uint32_t g_Qpk[H_ * 128 * 4 * 32 * 8];    // 8 MB
// Kpk: [h][j(512)][s(4)][lane(32)][4 u32]  {bh0,bh1,bl0,bl1}
__device__ __align__(16) uint32_t g_Kpk[H_ * 512 * 4 * 32 * 4];    // 16 MB
// Vpk: [h][tk(256)][j(16)][lane(32)][4 u32]  {vh0,vh1,vl0,vl1}
__device__ __align__(16) uint32_t g_Vpk[H_ * 256 * 16 * 32 * 4];   // 32 MB

// ---------------- helpers ----------------
__device__ __forceinline__ uint32_t s2u(const void* p) {
    uint32_t a;
    asm("{ .reg .u64 t; cvta.to.shared.u64 t, %1; cvt.u32.u64 %0, t; }" : "=r"(a) : "l"(p));
    return a;
}
__device__ __forceinline__ float fex2(float x) {
    float y; asm("ex2.approx.ftz.f32 %0, %1;" : "=f"(y) : "f"(x)); return y;
}
__device__ __forceinline__ uint32_t pk(__nv_bfloat16 a, __nv_bfloat16 b) {
    __nv_bfloat162 t = __halves2bfloat162(a, b);  // a -> low 16
    return *reinterpret_cast<uint32_t*>(&t);
}
__device__ __forceinline__ uint32_t pk_hi(float a, float b) {
    return pk(__float2bfloat16(a), __float2bfloat16(b));
}
__device__ __forceinline__ uint32_t pk_lo(float a, float b) {
    const __nv_bfloat16 ha = __float2bfloat16(a), hb = __float2bfloat16(b);
    return pk(__float2bfloat16(a - __bfloat162float(ha)),
              __float2bfloat16(b - __bfloat162float(hb)));
}
__device__ __forceinline__ void split(float v, __nv_bfloat16& h, __nv_bfloat16& l) {
    h = __float2bfloat16(v);
    l = __float2bfloat16(v - __bfloat162float(h));
}
// NOTE: non-volatile on purpose — pure register dataflow; lets ptxas
// software-pipeline independent MMAs across phases.
__device__ __forceinline__ void mma_bf16(float* c, const uint32_t* a,
                                         uint32_t b0, uint32_t b1) {
    asm("mma.sync.aligned.m16n8k16.row.col.f32.bf16.bf16.f32 "
        "{%0,%1,%2,%3}, {%4,%5,%6,%7}, {%8,%9}, {%0,%1,%2,%3};"
        : "+f"(c[0]), "+f"(c[1]), "+f"(c[2]), "+f"(c[3])
        : "r"(a[0]), "r"(a[1]), "r"(a[2]), "r"(a[3]), "r"(b0), "r"(b1));
}
#define CP16(d, s) asm volatile("cp.async.cg.shared.global [%0], [%1], 16;" \
                                :: "r"(d), "l"(s) : "memory")
#define CP_COMMIT() asm volatile("cp.async.commit_group;" ::: "memory")
#define CP_WAIT(n)  asm volatile("cp.async.wait_group %0;" :: "n"(n) : "memory")

// ---------------- prep: projection + split + pack (coalesced stores) ------
struct ProjSmem {
    float Rs[128 * 64];      // 32 KB
    float rowbuf[32 * 128];  // 16 KB
    float proj[32][65];      // 8.3 KB staged outputs
};
constexpr int PROJ_SMEM = sizeof(ProjSmem);

template <int ISQ>
__global__ void __launch_bounds__(256) proj_pack(
    const float* __restrict__ in, const float* __restrict__ R,
    uint32_t* __restrict__ outpk)
{
    extern __shared__ char sraw[];
    ProjSmem& sm = *reinterpret_cast<ProjSmem*>(sraw);
    const int tid = threadIdx.x, row0 = blockIdx.x * 32;
    #pragma unroll
    for (int i = 0; i < 32; i++) sm.Rs[tid + 256 * i] = R[tid + 256 * i];
    #pragma unroll
    for (int i = 0; i < 16; i++)
        sm.rowbuf[tid + 256 * i] = in[(size_t)row0 * 128 + tid + 256 * i];
    __syncthreads();

    const int p = tid & 63, rsub = tid >> 6;
    float acc[8];
    #pragma unroll
    for (int i = 0; i < 8; i++) acc[i] = 0.f;
    #pragma unroll 4
    for (int d = 0; d < 128; d++) {
        const float rv = sm.Rs[d * 64 + p];
        #pragma unroll
        for (int it = 0; it < 8; it++)
            acc[it] += sm.rowbuf[(rsub + 4 * it) * 128 + d] * rv;
    }
    #pragma unroll
    for (int it = 0; it < 8; it++) sm.proj[rsub + 4 * it][p] = acc[it];
    __syncthreads();

    if (ISQ) {
        const int h = row0 >> 11, strip0 = (row0 & 2047) >> 4;
        #pragma unroll
        for (int i = 0; i < 8; i++) {
            const int w = tid + 256 * i;
            const int strip_l = w >> 10, s = (w >> 8) & 3;
            const int lane = (w >> 3) & 31, widx = w & 7;
            const int wr = widx & 3, lohi = widx >> 2;
            const int row_l = strip_l * 16 + (wr & 1) * 8 + (lane >> 2);
            const int p0 = s * 16 + ((wr >> 1) & 1) * 8 + (lane & 3) * 2;
            const float a = sm.proj[row_l][p0], b = sm.proj[row_l][p0 + 1];
            const uint32_t word = lohi ? pk_lo(a, b) : pk_hi(a, b);
            outpk[((((size_t)h * 128 + strip0 + strip_l) * 4 + s) * 32 + lane) * 8 + widx] = word;
        }
    } else {
        const int h = row0 >> 12, j0 = (row0 & 4095) >> 3;
        #pragma unroll
        for (int i = 0; i < 8; i++) {
            const int w = tid + 256 * i;
            const int jj = w >> 9, s = (w >> 7) & 3;
            const int lane = (w >> 2) & 31, widx = w & 3;
            const int lohi = widx >> 1, hw = widx & 1;
            const int row_l = jj * 8 + (lane >> 2);
            const int p0 = s * 16 + hw * 8 + (lane & 3) * 2;
            const float a = sm.proj[row_l][p0], b = sm.proj[row_l][p0 + 1];
            const uint32_t word = lohi ? pk_lo(a, b) : pk_hi(a, b);
            outpk[((((size_t)h * 512 + j0 + jj) * 4 + s) * 32 + lane) * 4 + widx] = word;
        }
    }
}

// ---------------- prep: V split + pack (coalesced) ----------------
__global__ void __launch_bounds__(256) vpack(
    const float* __restrict__ V, uint32_t* __restrict__ outpk)
{
    __shared__ float vt[16][129];
    const int tid = threadIdx.x;
    const int h = blockIdx.x >> 8, tk = blockIdx.x & 255;
    const float* src = V + ((size_t)h * NKV_ + tk * 16) * D_;
    #pragma unroll
    for (int i = 0; i < 8; i++) {
        const int idx = tid + 256 * i;
        vt[idx >> 7][idx & 127] = src[idx];
    }
    __syncthreads();
    #pragma unroll
    for (int i = 0; i < 8; i++) {
        const int w = tid + 256 * i;
        const int j = w >> 7, lane = (w >> 2) & 31, widx = w & 3;
        const int hw = widx & 1, lohi = widx >> 1;
        const int kv0 = hw * 8 + (lane & 3) * 2, d = j * 8 + (lane >> 2);
        const float a = vt[kv0][d], b = vt[kv0 + 1][d];
        const uint32_t word = lohi ? pk_lo(a, b) : pk_hi(a, b);
        outpk[((((size_t)h * 256 + tk) * 16 + j) * 32 + lane) * 4 + widx] = word;
    }
}

// ---------------- flash attention (R5 shape + 1 barrier/tile + sched) ----
constexpr int KT_U32 = 16 * 4 * 32 * 4;        // 32 KB
constexpr int VT_U32 = 8 * 16 * 32 * 4;        // 64 KB
constexpr int BUF_U32 = KT_U32 + VT_U32;
constexpr int FLASH_SMEM = 2 * BUF_U32 * 4;    // 196608 B
constexpr int NT = NKV_ / 128;                 // 32 kv tiles

__device__ __forceinline__ void issue_tile(uint32_t* smem, int t, int h, int tid,
                                           const uint32_t* __restrict__ Kpk,
                                           const uint32_t* __restrict__ Vpk) {
    uint32_t* dst = smem + (t & 1) * BUF_U32;
    const uint32_t* ksrc = Kpk + ((size_t)h * 512 + (size_t)t * 16) * 512;
    const uint32_t* vsrc = Vpk + ((size_t)h * 256 + (size_t)t * 8) * 2048;
    const uint32_t ka = s2u(dst), va = s2u(dst + KT_U32);
    #pragma unroll
    for (int i = 0; i < 8; i++) {
        const int idx = tid + 256 * i;
        CP16(ka + idx * 16, ksrc + idx * 4);
    }
    #pragma unroll
    for (int i = 0; i < 16; i++) {
        const int idx = tid + 256 * i;
        CP16(va + idx * 16, vsrc + idx * 4);
    }
    CP_COMMIT();
}

__global__ void __launch_bounds__(256, 1) flash_mma(
    const uint32_t* __restrict__ Qpk, const uint32_t* __restrict__ Kpk,
    const uint32_t* __restrict__ Vpk, float* __restrict__ Og)
{
    extern __shared__ uint32_t smem[];
    const int tid = threadIdx.x, w = tid >> 5, lane = tid & 31;
    const int gid = lane >> 2, tig = lane & 3;
    const int h = blockIdx.y, q0 = blockIdx.x * 128;
    const int strip = (q0 >> 4) + w;

    uint32_t qh[4][4], ql[4][4];
    #pragma unroll
    for (int s = 0; s < 4; s++) {
        const uint32_t* qp = Qpk + ((((size_t)h * 128 + strip) * 4 + s) * 32 + lane) * 8;
        const uint4 a = *(const uint4*)qp;
        const uint4 b = *(const uint4*)(qp + 4);
        qh[s][0] = a.x; qh[s][1] = a.y; qh[s][2] = a.z; qh[s][3] = a.w;
        ql[s][0] = b.x; ql[s][1] = b.y; ql[s][2] = b.z; ql[s][3] = b.w;
    }

    float o[16][4];
    #pragma unroll
    for (int j = 0; j < 16; j++)
        #pragma unroll
        for (int r = 0; r < 4; r++) o[j][r] = 0.f;
    float lsum0 = 0.f, lsum1 = 0.f;

    issue_tile(smem, 0, h, tid, Kpk, Vpk);

    #pragma unroll 1
    for (int t = 0; t < NT; t++) {
        CP_WAIT(0);            // this tile's data arrived
        __syncthreads();       // all warps: tile t visible AND done reading buf (t+1)&1
        if (t + 1 < NT) issue_tile(smem, t + 1, h, tid, Kpk, Vpk);

        const uint32_t* kb = smem + (t & 1) * BUF_U32;
        const uint32_t* vb = kb + KT_U32;

        #pragma unroll
        for (int tk = 0; tk < 8; tk++) {
            // ---- S for j-pair (2tk, 2tk+1), exp -> P fragments ----
            uint32_t ph[4], pl[4];
            #pragma unroll
            for (int jj = 0; jj < 2; jj++) {
                const int j = tk * 2 + jj;
                float cA[4] = {0.f, 0.f, 0.f, 0.f};
                float cB[4] = {0.f, 0.f, 0.f, 0.f};
                {
                    const uint4 f0 = *(const uint4*)&kb[((j * 4 + 0) * 32 + lane) * 4];
                    mma_bf16(cA, qh[0], f0.x, f0.y);
                    mma_bf16(cA, ql[0], f0.x, f0.y);
                    mma_bf16(cA, qh[0], f0.z, f0.w);
                    const uint4 f1 = *(const uint4*)&kb[((j * 4 + 1) * 32 + lane) * 4];
                    mma_bf16(cB, qh[1], f1.x, f1.y);
                    mma_bf16(cB, ql[1], f1.x, f1.y);
                    mma_bf16(cB, qh[1], f1.z, f1.w);
                    const uint4 f2 = *(const uint4*)&kb[((j * 4 + 2) * 32 + lane) * 4];
                    mma_bf16(cA, qh[2], f2.x, f2.y);
                    mma_bf16(cA, ql[2], f2.x, f2.y);
                    mma_bf16(cA, qh[2], f2.z, f2.w);
                    const uint4 f3 = *(const uint4*)&kb[((j * 4 + 3) * 32 + lane) * 4];
                    mma_bf16(cB, qh[3], f3.x, f3.y);
                    mma_bf16(cB, ql[3], f3.x, f3.y);
                    mma_bf16(cB, qh[3], f3.z, f3.w);
                }
                const float e0 = fex2((cA[0] + cB[0]) * SC2);
                const float e1 = fex2((cA[1] + cB[1]) * SC2);
                const float e2 = fex2((cA[2] + cB[2]) * SC2);
                const float e3 = fex2((cA[3] + cB[3]) * SC2);
                lsum0 += e0 + e1;
                lsum1 += e2 + e3;
                __nv_bfloat16 h0, l0, h1, l1, h2, l2, h3, l3;
                split(e0, h0, l0); split(e1, h1, l1);
                split(e2, h2, l2); split(e3, h3, l3);
                ph[jj * 2] = pk(h0, h1); ph[jj * 2 + 1] = pk(h2, h3);
                pl[jj * 2] = pk(l0, l1); pl[jj * 2 + 1] = pk(l2, l3);
            }
            // ---- O += P(:, tk-chunk) @ V(tk-chunk, :) ----
            #pragma unroll
            for (int j = 0; j < 16; j++) {
                const uint4 f = *(const uint4*)&vb[((tk * 16 + j) * 32 + lane) * 4];
                mma_bf16(o[j], ph, f.x, f.y);   // Ph * Vh
                mma_bf16(o[j], pl, f.x, f.y);   // Pl * Vh
                mma_bf16(o[j], ph, f.z, f.w);   // Ph * Vl
            }
        }
    }

    // ---- epilogue ----
    lsum0 += __shfl_xor_sync(0xffffffffu, lsum0, 1);
    lsum0 += __shfl_xor_sync(0xffffffffu, lsum0, 2);
    lsum1 += __shfl_xor_sync(0xffffffffu, lsum1, 1);
    lsum1 += __shfl_xor_sync(0xffffffffu, lsum1, 2);
    const float inv0 = 1.0f / lsum0, inv1 = 1.0f / lsum1;

    const int row0 = h * NQ_ + q0 + w * 16 + gid;
    #pragma unroll
    for (int j = 0; j < 16; j++) {
        const float2 v0 = make_float2(o[j][0] * inv0, o[j][1] * inv0);
        const float2 v1 = make_float2(o[j][2] * inv1, o[j][3] * inv1);
        *(float2*)(Og + (size_t)row0 * 128 + j * 8 + tig * 2) = v0;
        *(float2*)(Og + (size_t)(row0 + 8) * 128 + j * 8 + tig * 2) = v1;
    }
}

// ---------------- launch ----------------
extern "C" void kernel_launch(void* const* d_in, const int* in_sizes, int n_in,
                              void* d_out, int out_size)
{
    const float* Q = (const float*)d_in[0];
    const float* K = (const float*)d_in[1];
    const float* V = (const float*)d_in[2];
    const float* R = (const float*)d_in[3];
    float* O = (float*)d_out;

    uint32_t *qpk, *kpk, *vpk;
    cudaGetSymbolAddress((void**)&qpk, g_Qpk);
    cudaGetSymbolAddress((void**)&kpk, g_Kpk);
    cudaGetSymbolAddress((void**)&vpk, g_Vpk);

    cudaFuncSetAttribute(proj_pack<1>, cudaFuncAttributeMaxDynamicSharedMemorySize, PROJ_SMEM);
    cudaFuncSetAttribute(proj_pack<0>, cudaFuncAttributeMaxDynamicSharedMemorySize, PROJ_SMEM);
    cudaFuncSetAttribute(flash_mma, cudaFuncAttributeMaxDynamicSharedMemorySize, FLASH_SMEM);

    proj_pack<1><<<(H_ * NQ_) / 32, 256, PROJ_SMEM>>>(Q, R, qpk);
    proj_pack<0><<<(H_ * NKV_) / 32, 256, PROJ_SMEM>>>(K, R, kpk);
    vpack<<<H_ * 256, 256>>>(V, vpk);
    flash_mma<<<dim3(NQ_ / 128, H_), 256, FLASH_SMEM>>>(qpk, kpk, vpk, O);
}

// round 9
// speedup vs baseline: 1.4463x; 1.0176x over previous
#include <cuda_runtime.h>
#include <cuda_bf16.h>
#include <cstdint>

// ---------------- fixed shapes ----------------
constexpr int H_ = 16, NQ_ = 2048, NKV_ = 4096, D_ = 128, PD_ = 64;
constexpr float SC2 = 0.18033688011112042f;  // 0.125 * log2(e)

// ---------------- packed fragment buffers (gmem scratch, no cudaMalloc) ----
// Qpk: [h][strip(128)][s(4)][lane(32)][8 u32]  (0-3 hi a0..a3, 4-7 lo)
__device__ __align__(16) uint32_t g_Qpk[H_ * 128 * 4 * 32 * 8];    // 8 MB
// Kpk: [h][j(512)][s(4)][lane(32)][4 u32]  {bh0,bh1,bl0,bl1}
__device__ __align__(16) uint32_t g_Kpk[H_ * 512 * 4 * 32 * 4];    // 16 MB
// Vpk: [h][tk(256)][j(16)][lane(32)][4 u32]  {vh0,vh1,vl0,vl1}
__device__ __align__(16) uint32_t g_Vpk[H_ * 256 * 16 * 32 * 4];   // 32 MB

// ---------------- helpers ----------------
__device__ __forceinline__ uint32_t s2u(const void* p) {
    uint32_t a;
    asm("{ .reg .u64 t; cvta.to.shared.u64 t, %1; cvt.u32.u64 %0, t; }" : "=r"(a) : "l"(p));
    return a;
}
__device__ __forceinline__ float fex2(float x) {
    float y; asm("ex2.approx.ftz.f32 %0, %1;" : "=f"(y) : "f"(x)); return y;
}
__device__ __forceinline__ uint32_t pk(__nv_bfloat16 a, __nv_bfloat16 b) {
    __nv_bfloat162 t = __halves2bfloat162(a, b);  // a -> low 16
    return *reinterpret_cast<uint32_t*>(&t);
}
__device__ __forceinline__ uint32_t pk_hi(float a, float b) {
    return pk(__float2bfloat16(a), __float2bfloat16(b));
}
__device__ __forceinline__ uint32_t pk_lo(float a, float b) {
    const __nv_bfloat16 ha = __float2bfloat16(a), hb = __float2bfloat16(b);
    return pk(__float2bfloat16(a - __bfloat162float(ha)),
              __float2bfloat16(b - __bfloat162float(hb)));
}
// pack (a,b) -> hi word (a low half) and lo-residual word, using bf16x2 cvt
__device__ __forceinline__ void pack2(float a, float b, uint32_t& hi, uint32_t& lo) {
    uint32_t h;
    asm("cvt.rn.bf16x2.f32 %0, %1, %2;" : "=r"(h) : "f"(b), "f"(a));  // b->hi, a->lo
    const float ha = __uint_as_float(h << 16);
    const float hb = __uint_as_float(h & 0xFFFF0000u);
    const float la = a - ha, lb = b - hb;
    uint32_t l;
    asm("cvt.rn.bf16x2.f32 %0, %1, %2;" : "=r"(l) : "f"(lb), "f"(la));
    hi = h; lo = l;
}
// non-volatile: pure register dataflow, ptxas free to schedule
__device__ __forceinline__ void mma_bf16(float* c, const uint32_t* a,
                                         uint32_t b0, uint32_t b1) {
    asm("mma.sync.aligned.m16n8k16.row.col.f32.bf16.bf16.f32 "
        "{%0,%1,%2,%3}, {%4,%5,%6,%7}, {%8,%9}, {%0,%1,%2,%3};"
        : "+f"(c[0]), "+f"(c[1]), "+f"(c[2]), "+f"(c[3])
        : "r"(a[0]), "r"(a[1]), "r"(a[2]), "r"(a[3]), "r"(b0), "r"(b1));
}
#define CP16(d, s) asm volatile("cp.async.cg.shared.global [%0], [%1], 16;" \
                                :: "r"(d), "l"(s) : "memory")
#define CP_COMMIT() asm volatile("cp.async.commit_group;" ::: "memory")
#define CP_WAIT(n)  asm volatile("cp.async.wait_group %0;" :: "n"(n) : "memory")

// ---------------- prep: projection + split + pack (coalesced stores) ------
struct ProjSmem {
    float Rs[128 * 64];      // 32 KB
    float rowbuf[32 * 128];  // 16 KB
    float proj[32][65];      // 8.3 KB staged outputs
};
constexpr int PROJ_SMEM = sizeof(ProjSmem);

template <int ISQ>
__global__ void __launch_bounds__(256) proj_pack(
    const float* __restrict__ in, const float* __restrict__ R,
    uint32_t* __restrict__ outpk)
{
    extern __shared__ char sraw[];
    ProjSmem& sm = *reinterpret_cast<ProjSmem*>(sraw);
    const int tid = threadIdx.x, row0 = blockIdx.x * 32;
    #pragma unroll
    for (int i = 0; i < 32; i++) sm.Rs[tid + 256 * i] = R[tid + 256 * i];
    #pragma unroll
    for (int i = 0; i < 16; i++)
        sm.rowbuf[tid + 256 * i] = in[(size_t)row0 * 128 + tid + 256 * i];
    __syncthreads();

    const int p = tid & 63, rsub = tid >> 6;
    float acc[8];
    #pragma unroll
    for (int i = 0; i < 8; i++) acc[i] = 0.f;
    #pragma unroll 4
    for (int d = 0; d < 128; d++) {
        const float rv = sm.Rs[d * 64 + p];
        #pragma unroll
        for (int it = 0; it < 8; it++)
            acc[it] += sm.rowbuf[(rsub + 4 * it) * 128 + d] * rv;
    }
    #pragma unroll
    for (int it = 0; it < 8; it++) sm.proj[rsub + 4 * it][p] = acc[it];
    __syncthreads();

    if (ISQ) {
        const int h = row0 >> 11, strip0 = (row0 & 2047) >> 4;
        #pragma unroll
        for (int i = 0; i < 8; i++) {
            const int w = tid + 256 * i;
            const int strip_l = w >> 10, s = (w >> 8) & 3;
            const int lane = (w >> 3) & 31, widx = w & 7;
            const int wr = widx & 3, lohi = widx >> 2;
            const int row_l = strip_l * 16 + (wr & 1) * 8 + (lane >> 2);
            const int p0 = s * 16 + ((wr >> 1) & 1) * 8 + (lane & 3) * 2;
            const float a = sm.proj[row_l][p0], b = sm.proj[row_l][p0 + 1];
            const uint32_t word = lohi ? pk_lo(a, b) : pk_hi(a, b);
            outpk[((((size_t)h * 128 + strip0 + strip_l) * 4 + s) * 32 + lane) * 8 + widx] = word;
        }
    } else {
        const int h = row0 >> 12, j0 = (row0 & 4095) >> 3;
        #pragma unroll
        for (int i = 0; i < 8; i++) {
            const int w = tid + 256 * i;
            const int jj = w >> 9, s = (w >> 7) & 3;
            const int lane = (w >> 2) & 31, widx = w & 3;
            const int lohi = widx >> 1, hw = widx & 1;
            const int row_l = jj * 8 + (lane >> 2);
            const int p0 = s * 16 + hw * 8 + (lane & 3) * 2;
            const float a = sm.proj[row_l][p0], b = sm.proj[row_l][p0 + 1];
            const uint32_t word = lohi ? pk_lo(a, b) : pk_hi(a, b);
            outpk[((((size_t)h * 512 + j0 + jj) * 4 + s) * 32 + lane) * 4 + widx] = word;
        }
    }
}

// ---------------- prep: V split + pack (coalesced) ----------------
__global__ void __launch_bounds__(256) vpack(
    const float* __restrict__ V, uint32_t* __restrict__ outpk)
{
    __shared__ float vt[16][129];
    const int tid = threadIdx.x;
    const int h = blockIdx.x >> 8, tk = blockIdx.x & 255;
    const float* src = V + ((size_t)h * NKV_ + tk * 16) * D_;
    #pragma unroll
    for (int i = 0; i < 8; i++) {
        const int idx = tid + 256 * i;
        vt[idx >> 7][idx & 127] = src[idx];
    }
    __syncthreads();
    #pragma unroll
    for (int i = 0; i < 8; i++) {
        const int w = tid + 256 * i;
        const int j = w >> 7, lane = (w >> 2) & 31, widx = w & 3;
        const int hw = widx & 1, lohi = widx >> 1;
        const int kv0 = hw * 8 + (lane & 3) * 2, d = j * 8 + (lane >> 2);
        const float a = vt[kv0][d], b = vt[kv0 + 1][d];
        const uint32_t word = lohi ? pk_lo(a, b) : pk_hi(a, b);
        outpk[((((size_t)h * 256 + tk) * 16 + j) * 32 + lane) * 4 + widx] = word;
    }
}

// ---------------- flash attention (tk-staggered warps) ----------
constexpr int KT_U32 = 16 * 4 * 32 * 4;        // 32 KB
constexpr int VT_U32 = 8 * 16 * 32 * 4;        // 64 KB
constexpr int BUF_U32 = KT_U32 + VT_U32;
constexpr int FLASH_SMEM = 2 * BUF_U32 * 4;    // 196608 B
constexpr int NT = NKV_ / 128;                 // 32 kv tiles

__device__ __forceinline__ void issue_tile(uint32_t* smem, int t, int h, int tid,
                                           const uint32_t* __restrict__ Kpk,
                                           const uint32_t* __restrict__ Vpk) {
    uint32_t* dst = smem + (t & 1) * BUF_U32;
    const uint32_t* ksrc = Kpk + ((size_t)h * 512 + (size_t)t * 16) * 512;
    const uint32_t* vsrc = Vpk + ((size_t)h * 256 + (size_t)t * 8) * 2048;
    const uint32_t ka = s2u(dst), va = s2u(dst + KT_U32);
    #pragma unroll
    for (int i = 0; i < 8; i++) {
        const int idx = tid + 256 * i;
        CP16(ka + idx * 16, ksrc + idx * 4);
    }
    #pragma unroll
    for (int i = 0; i < 16; i++) {
        const int idx = tid + 256 * i;
        CP16(va + idx * 16, vsrc + idx * 4);
    }
    CP_COMMIT();
}

__global__ void __launch_bounds__(256, 1) flash_mma(
    const uint32_t* __restrict__ Qpk, const uint32_t* __restrict__ Kpk,
    const uint32_t* __restrict__ Vpk, float* __restrict__ Og)
{
    extern __shared__ uint32_t smem[];
    const int tid = threadIdx.x, w = tid >> 5, lane = tid & 31;
    const int gid = lane >> 2, tig = lane & 3;
    const int h = blockIdx.y, q0 = blockIdx.x * 128;
    const int strip = (q0 >> 4) + w;
    const int tkoff = (w >> 2) * 4;   // warps sharing an SMSP (w, w+4) anti-phase

    uint32_t qh[4][4], ql[4][4];
    #pragma unroll
    for (int s = 0; s < 4; s++) {
        const uint32_t* qp = Qpk + ((((size_t)h * 128 + strip) * 4 + s) * 32 + lane) * 8;
        const uint4 a = *(const uint4*)qp;
        const uint4 b = *(const uint4*)(qp + 4);
        qh[s][0] = a.x; qh[s][1] = a.y; qh[s][2] = a.z; qh[s][3] = a.w;
        ql[s][0] = b.x; ql[s][1] = b.y; ql[s][2] = b.z; ql[s][3] = b.w;
    }

    float o[16][4];
    #pragma unroll
    for (int j = 0; j < 16; j++)
        #pragma unroll
        for (int r = 0; r < 4; r++) o[j][r] = 0.f;
    float lsum0 = 0.f, lsum1 = 0.f;

    issue_tile(smem, 0, h, tid, Kpk, Vpk);

    #pragma unroll 1
    for (int t = 0; t < NT; t++) {
        CP_WAIT(0);
        __syncthreads();
        if (t + 1 < NT) issue_tile(smem, t + 1, h, tid, Kpk, Vpk);

        const uint32_t* kb = smem + (t & 1) * BUF_U32;
        const uint32_t* vb = kb + KT_U32;

        #pragma unroll
        for (int tki = 0; tki < 8; tki++) {
            const int tk = (tki + tkoff) & 7;
            // ---- S for j-pair (2tk, 2tk+1), exp -> P fragments ----
            uint32_t ph[4], pl[4];
            #pragma unroll
            for (int jj = 0; jj < 2; jj++) {
                const int j = tk * 2 + jj;
                float cA[4] = {0.f, 0.f, 0.f, 0.f};
                float cB[4] = {0.f, 0.f, 0.f, 0.f};
                {
                    const uint4 f0 = *(const uint4*)&kb[((j * 4 + 0) * 32 + lane) * 4];
                    mma_bf16(cA, qh[0], f0.x, f0.y);
                    mma_bf16(cA, ql[0], f0.x, f0.y);
                    mma_bf16(cA, qh[0], f0.z, f0.w);
                    const uint4 f1 = *(const uint4*)&kb[((j * 4 + 1) * 32 + lane) * 4];
                    mma_bf16(cB, qh[1], f1.x, f1.y);
                    mma_bf16(cB, ql[1], f1.x, f1.y);
                    mma_bf16(cB, qh[1], f1.z, f1.w);
                    const uint4 f2 = *(const uint4*)&kb[((j * 4 + 2) * 32 + lane) * 4];
                    mma_bf16(cA, qh[2], f2.x, f2.y);
                    mma_bf16(cA, ql[2], f2.x, f2.y);
                    mma_bf16(cA, qh[2], f2.z, f2.w);
                    const uint4 f3 = *(const uint4*)&kb[((j * 4 + 3) * 32 + lane) * 4];
                    mma_bf16(cB, qh[3], f3.x, f3.y);
                    mma_bf16(cB, ql[3], f3.x, f3.y);
                    mma_bf16(cB, qh[3], f3.z, f3.w);
                }
                const float e0 = fex2((cA[0] + cB[0]) * SC2);
                const float e1 = fex2((cA[1] + cB[1]) * SC2);
                const float e2 = fex2((cA[2] + cB[2]) * SC2);
                const float e3 = fex2((cA[3] + cB[3]) * SC2);
                lsum0 += e0 + e1;
                lsum1 += e2 + e3;
                pack2(e0, e1, ph[jj * 2], pl[jj * 2]);
                pack2(e2, e3, ph[jj * 2 + 1], pl[jj * 2 + 1]);
            }
            // ---- O += P(:, tk-chunk) @ V(tk-chunk, :) ----
            #pragma unroll
            for (int j = 0; j < 16; j++) {
                const uint4 f = *(const uint4*)&vb[((tk * 16 + j) * 32 + lane) * 4];
                mma_bf16(o[j], ph, f.x, f.y);   // Ph * Vh
                mma_bf16(o[j], pl, f.x, f.y);   // Pl * Vh
                mma_bf16(o[j], ph, f.z, f.w);   // Ph * Vl
            }
        }
    }

    // ---- epilogue ----
    lsum0 += __shfl_xor_sync(0xffffffffu, lsum0, 1);
    lsum0 += __shfl_xor_sync(0xffffffffu, lsum0, 2);
    lsum1 += __shfl_xor_sync(0xffffffffu, lsum1, 1);
    lsum1 += __shfl_xor_sync(0xffffffffu, lsum1, 2);
    const float inv0 = 1.0f / lsum0, inv1 = 1.0f / lsum1;

    const int row0 = h * NQ_ + q0 + w * 16 + gid;
    #pragma unroll
    for (int j = 0; j < 16; j++) {
        const float2 v0 = make_float2(o[j][0] * inv0, o[j][1] * inv0);
        const float2 v1 = make_float2(o[j][2] * inv1, o[j][3] * inv1);
        *(float2*)(Og + (size_t)row0 * 128 + j * 8 + tig * 2) = v0;
        *(float2*)(Og + (size_t)(row0 + 8) * 128 + j * 8 + tig * 2) = v1;
    }
}

// ---------------- launch ----------------
extern "C" void kernel_launch(void* const* d_in, const int* in_sizes, int n_in,
                              void* d_out, int out_size)
{
    const float* Q = (const float*)d_in[0];
    const float* K = (const float*)d_in[1];
    const float* V = (const float*)d_in[2];
    const float* R = (const float*)d_in[3];
    float* O = (float*)d_out;

    uint32_t *qpk, *kpk, *vpk;
    cudaGetSymbolAddress((void**)&qpk, g_Qpk);
    cudaGetSymbolAddress((void**)&kpk, g_Kpk);
    cudaGetSymbolAddress((void**)&vpk, g_Vpk);

    cudaFuncSetAttribute(proj_pack<1>, cudaFuncAttributeMaxDynamicSharedMemorySize, PROJ_SMEM);
    cudaFuncSetAttribute(proj_pack<0>, cudaFuncAttributeMaxDynamicSharedMemorySize, PROJ_SMEM);
    cudaFuncSetAttribute(flash_mma, cudaFuncAttributeMaxDynamicSharedMemorySize, FLASH_SMEM);

    proj_pack<1><<<(H_ * NQ_) / 32, 256, PROJ_SMEM>>>(Q, R, qpk);
    proj_pack<0><<<(H_ * NKV_) / 32, 256, PROJ_SMEM>>>(K, R, kpk);
    vpack<<<H_ * 256, 256>>>(V, vpk);
    flash_mma<<<dim3(NQ_ / 128, H_), 256, FLASH_SMEM>>>(qpk, kpk, vpk, O);
}

// round 11
// speedup vs baseline: 1.6657x; 1.1517x over previous
#include <cuda_runtime.h>
#include <cuda_bf16.h>
#include <cstdint>

// ---------------- fixed shapes ----------------
constexpr int H_ = 16, NQ_ = 2048, NKV_ = 4096, D_ = 128, PD_ = 64;
constexpr float SC2 = 0.18033688011112042f;  // 0.125 * log2(e)

// ---------------- packed fragment buffers (gmem scratch, no cudaMalloc) ----
// Qpk: [h][strip(128)][s(4)][lane(32)][8 u32]  (0-3 hi a0..a3, 4-7 lo)
__device__ __align__(16) uint32_t g_Qpk[H_ * 128 * 4 * 32 * 8];    // 8 MB
// Kpk: [h][j(512)][s(4)][lane(32)][4 u32]  {bh0,bh1,bl0,bl1}
__device__ __align__(16) uint32_t g_Kpk[H_ * 512 * 4 * 32 * 4];    // 16 MB
// Vpk (tf32): [h][tk(256)][j(16)][lane(32)][4 u32] {g0b0,g0b1,g1b0,g1b1}
__device__ __align__(16) uint32_t g_Vpk[H_ * 256 * 16 * 32 * 4];   // 32 MB

// ---------------- helpers ----------------
__device__ __forceinline__ uint32_t s2u(const void* p) {
    uint32_t a;
    asm("{ .reg .u64 t; cvta.to.shared.u64 t, %1; cvt.u32.u64 %0, t; }" : "=r"(a) : "l"(p));
    return a;
}
__device__ __forceinline__ float fex2(float x) {
    float y; asm("ex2.approx.ftz.f32 %0, %1;" : "=f"(y) : "f"(x)); return y;
}
__device__ __forceinline__ uint32_t cvt_tf32(float x) {
    uint32_t u; asm("cvt.rna.tf32.f32 %0, %1;" : "=r"(u) : "f"(x)); return u;
}
__device__ __forceinline__ uint32_t pk(__nv_bfloat16 a, __nv_bfloat16 b) {
    __nv_bfloat162 t = __halves2bfloat162(a, b);  // a -> low 16
    return *reinterpret_cast<uint32_t*>(&t);
}
__device__ __forceinline__ uint32_t pk_hi(float a, float b) {
    return pk(__float2bfloat16(a), __float2bfloat16(b));
}
__device__ __forceinline__ uint32_t pk_lo(float a, float b) {
    const __nv_bfloat16 ha = __float2bfloat16(a), hb = __float2bfloat16(b);
    return pk(__float2bfloat16(a - __bfloat162float(ha)),
              __float2bfloat16(b - __bfloat162float(hb)));
}
// non-volatile: pure register dataflow, ptxas free to schedule
__device__ __forceinline__ void mma_bf16(float* c, const uint32_t* a,
                                         uint32_t b0, uint32_t b1) {
    asm("mma.sync.aligned.m16n8k16.row.col.f32.bf16.bf16.f32 "
        "{%0,%1,%2,%3}, {%4,%5,%6,%7}, {%8,%9}, {%0,%1,%2,%3};"
        : "+f"(c[0]), "+f"(c[1]), "+f"(c[2]), "+f"(c[3])
        : "r"(a[0]), "r"(a[1]), "r"(a[2]), "r"(a[3]), "r"(b0), "r"(b1));
}
__device__ __forceinline__ void mma_tf32(float* c, const uint32_t* a,
                                         uint32_t b0, uint32_t b1) {
    asm("mma.sync.aligned.m16n8k8.row.col.f32.tf32.tf32.f32 "
        "{%0,%1,%2,%3}, {%4,%5,%6,%7}, {%8,%9}, {%0,%1,%2,%3};"
        : "+f"(c[0]), "+f"(c[1]), "+f"(c[2]), "+f"(c[3])
        : "r"(a[0]), "r"(a[1]), "r"(a[2]), "r"(a[3]), "r"(b0), "r"(b1));
}
#define CP16(d, s) asm volatile("cp.async.cg.shared.global [%0], [%1], 16;" \
                                :: "r"(d), "l"(s) : "memory")
#define CP_COMMIT() asm volatile("cp.async.commit_group;" ::: "memory")
#define CP_WAIT(n)  asm volatile("cp.async.wait_group %0;" :: "n"(n) : "memory")

// ---------------- prep: projection + split + pack (coalesced stores) ------
struct ProjSmem {
    float Rs[128 * 64];      // 32 KB
    float rowbuf[32 * 128];  // 16 KB
    float proj[32][65];      // 8.3 KB staged outputs
};
constexpr int PROJ_SMEM = sizeof(ProjSmem);

template <int ISQ>
__global__ void __launch_bounds__(256) proj_pack(
    const float* __restrict__ in, const float* __restrict__ R,
    uint32_t* __restrict__ outpk)
{
    extern __shared__ char sraw[];
    ProjSmem& sm = *reinterpret_cast<ProjSmem*>(sraw);
    const int tid = threadIdx.x, row0 = blockIdx.x * 32;
    #pragma unroll
    for (int i = 0; i < 32; i++) sm.Rs[tid + 256 * i] = R[tid + 256 * i];
    #pragma unroll
    for (int i = 0; i < 16; i++)
        sm.rowbuf[tid + 256 * i] = in[(size_t)row0 * 128 + tid + 256 * i];
    __syncthreads();

    const int p = tid & 63, rsub = tid >> 6;
    float acc[8];
    #pragma unroll
    for (int i = 0; i < 8; i++) acc[i] = 0.f;
    #pragma unroll 4
    for (int d = 0; d < 128; d++) {
        const float rv = sm.Rs[d * 64 + p];
        #pragma unroll
        for (int it = 0; it < 8; it++)
            acc[it] += sm.rowbuf[(rsub + 4 * it) * 128 + d] * rv;
    }
    #pragma unroll
    for (int it = 0; it < 8; it++) sm.proj[rsub + 4 * it][p] = acc[it];
    __syncthreads();

    if (ISQ) {
        const int h = row0 >> 11, strip0 = (row0 & 2047) >> 4;
        #pragma unroll
        for (int i = 0; i < 8; i++) {
            const int w = tid + 256 * i;
            const int strip_l = w >> 10, s = (w >> 8) & 3;
            const int lane = (w >> 3) & 31, widx = w & 7;
            const int wr = widx & 3, lohi = widx >> 2;
            const int row_l = strip_l * 16 + (wr & 1) * 8 + (lane >> 2);
            const int p0 = s * 16 + ((wr >> 1) & 1) * 8 + (lane & 3) * 2;
            const float a = sm.proj[row_l][p0], b = sm.proj[row_l][p0 + 1];
            const uint32_t word = lohi ? pk_lo(a, b) : pk_hi(a, b);
            outpk[((((size_t)h * 128 + strip0 + strip_l) * 4 + s) * 32 + lane) * 8 + widx] = word;
        }
    } else {
        const int h = row0 >> 12, j0 = (row0 & 4095) >> 3;
        #pragma unroll
        for (int i = 0; i < 8; i++) {
            const int w = tid + 256 * i;
            const int jj = w >> 9, s = (w >> 7) & 3;
            const int lane = (w >> 2) & 31, widx = w & 3;
            const int lohi = widx >> 1, hw = widx & 1;
            const int row_l = jj * 8 + (lane >> 2);
            const int p0 = s * 16 + hw * 8 + (lane & 3) * 2;
            const float a = sm.proj[row_l][p0], b = sm.proj[row_l][p0 + 1];
            const uint32_t word = lohi ? pk_lo(a, b) : pk_hi(a, b);
            outpk[((((size_t)h * 512 + j0 + jj) * 4 + s) * 32 + lane) * 4 + widx] = word;
        }
    }
}

// ---------------- prep: V -> tf32 B-fragments, kv rows permuted -----------
// B-frag m16n8k8: b0 = (k=tig, col=gid), b1 = (k=tig+4, col=gid).
// kv(κ) = 2κ for κ<4, 2(κ-4)+1 for κ>=4  (matches S C-frag cols 2tig, 2tig+1).
__global__ void __launch_bounds__(256) vpack(
    const float* __restrict__ V, uint32_t* __restrict__ outpk)
{
    __shared__ float vt[16][129];
    const int tid = threadIdx.x;
    const int h = blockIdx.x >> 8, tk = blockIdx.x & 255;
    const float* src = V + ((size_t)h * NKV_ + tk * 16) * D_;
    #pragma unroll
    for (int i = 0; i < 8; i++) {
        const int idx = tid + 256 * i;
        vt[idx >> 7][idx & 127] = src[idx];
    }
    __syncthreads();
    #pragma unroll
    for (int i = 0; i < 8; i++) {
        const int w = tid + 256 * i;
        const int j = w >> 7, lane = (w >> 2) & 31, widx = w & 3;
        const int g = widx >> 1, bslot = widx & 1, tig = lane & 3;
        const int kv_l = g * 8 + 2 * tig + bslot;   // permuted row order
        const int d = j * 8 + (lane >> 2);
        outpk[((((size_t)h * 256 + tk) * 16 + j) * 32 + lane) * 4 + widx] =
            cvt_tf32(vt[kv_l][d]);
    }
}

// ---------------- flash attention (bf16-split S, tf32 PV) ----------------
constexpr int KT_U32 = 16 * 4 * 32 * 4;        // 32 KB
constexpr int VT_U32 = 8 * 16 * 32 * 4;        // 64 KB
constexpr int BUF_U32 = KT_U32 + VT_U32;
constexpr int FLASH_SMEM = 2 * BUF_U32 * 4;    // 196608 B
constexpr int NT = NKV_ / 128;                 // 32 kv tiles

__device__ __forceinline__ void issue_tile(uint32_t* smem, int t, int h, int tid,
                                           const uint32_t* __restrict__ Kpk,
                                           const uint32_t* __restrict__ Vpk) {
    uint32_t* dst = smem + (t & 1) * BUF_U32;
    const uint32_t* ksrc = Kpk + ((size_t)h * 512 + (size_t)t * 16) * 512;
    const uint32_t* vsrc = Vpk + ((size_t)h * 256 + (size_t)t * 8) * 2048;
    const uint32_t ka = s2u(dst), va = s2u(dst + KT_U32);
    #pragma unroll
    for (int i = 0; i < 8; i++) {
        const int idx = tid + 256 * i;
        CP16(ka + idx * 16, ksrc + idx * 4);
    }
    #pragma unroll
    for (int i = 0; i < 16; i++) {
        const int idx = tid + 256 * i;
        CP16(va + idx * 16, vsrc + idx * 4);
    }
    CP_COMMIT();
}

__global__ void __launch_bounds__(256, 1) flash_mma(
    const uint32_t* __restrict__ Qpk, const uint32_t* __restrict__ Kpk,
    const uint32_t* __restrict__ Vpk, float* __restrict__ Og)
{
    extern __shared__ uint32_t smem[];
    const int tid = threadIdx.x, w = tid >> 5, lane = tid & 31;
    const int gid = lane >> 2, tig = lane & 3;
    const int h = blockIdx.y, q0 = blockIdx.x * 128;
    const int strip = (q0 >> 4) + w;
    const int tkoff = (w >> 2) * 4;   // warps sharing an SMSP anti-phase

    uint32_t qh[4][4], ql[4][4];
    #pragma unroll
    for (int s = 0; s < 4; s++) {
        const uint32_t* qp = Qpk + ((((size_t)h * 128 + strip) * 4 + s) * 32 + lane) * 8;
        const uint4 a = *(const uint4*)qp;
        const uint4 b = *(const uint4*)(qp + 4);
        qh[s][0] = a.x; qh[s][1] = a.y; qh[s][2] = a.z; qh[s][3] = a.w;
        ql[s][0] = b.x; ql[s][1] = b.y; ql[s][2] = b.z; ql[s][3] = b.w;
    }

    float o[16][4];
    #pragma unroll
    for (int j = 0; j < 16; j++)
        #pragma unroll
        for (int r = 0; r < 4; r++) o[j][r] = 0.f;
    float lsum0 = 0.f, lsum1 = 0.f;

    issue_tile(smem, 0, h, tid, Kpk, Vpk);

    #pragma unroll 1
    for (int t = 0; t < NT; t++) {
        CP_WAIT(0);
        __syncthreads();
        if (t + 1 < NT) issue_tile(smem, t + 1, h, tid, Kpk, Vpk);

        const uint32_t* kb = smem + (t & 1) * BUF_U32;
        const uint32_t* vb = kb + KT_U32;

        #pragma unroll
        for (int tki = 0; tki < 8; tki++) {
            const int tk = (tki + tkoff) & 7;
            // ---- S for j-pair (2tk, 2tk+1), exp -> tf32 A fragments ----
            uint32_t aP[2][4];
            #pragma unroll
            for (int jj = 0; jj < 2; jj++) {
                const int j = tk * 2 + jj;
                float cA[4] = {0.f, 0.f, 0.f, 0.f};
                float cB[4] = {0.f, 0.f, 0.f, 0.f};
                {
                    const uint4 f0 = *(const uint4*)&kb[((j * 4 + 0) * 32 + lane) * 4];
                    mma_bf16(cA, qh[0], f0.x, f0.y);
                    mma_bf16(cA, ql[0], f0.x, f0.y);
                    mma_bf16(cA, qh[0], f0.z, f0.w);
                    const uint4 f1 = *(const uint4*)&kb[((j * 4 + 1) * 32 + lane) * 4];
                    mma_bf16(cB, qh[1], f1.x, f1.y);
                    mma_bf16(cB, ql[1], f1.x, f1.y);
                    mma_bf16(cB, qh[1], f1.z, f1.w);
                    const uint4 f2 = *(const uint4*)&kb[((j * 4 + 2) * 32 + lane) * 4];
                    mma_bf16(cA, qh[2], f2.x, f2.y);
                    mma_bf16(cA, ql[2], f2.x, f2.y);
                    mma_bf16(cA, qh[2], f2.z, f2.w);
                    const uint4 f3 = *(const uint4*)&kb[((j * 4 + 3) * 32 + lane) * 4];
                    mma_bf16(cB, qh[3], f3.x, f3.y);
                    mma_bf16(cB, ql[3], f3.x, f3.y);
                    mma_bf16(cB, qh[3], f3.z, f3.w);
                }
                const float e0 = fex2((cA[0] + cB[0]) * SC2);  // (gid,   2tig)
                const float e1 = fex2((cA[1] + cB[1]) * SC2);  // (gid,   2tig+1)
                const float e2 = fex2((cA[2] + cB[2]) * SC2);  // (gid+8, 2tig)
                const float e3 = fex2((cA[3] + cB[3]) * SC2);  // (gid+8, 2tig+1)
                lsum0 += e0 + e1;
                lsum1 += e2 + e3;
                // tf32 A-frag: a0=(gid,k=tig) a1=(gid+8,k=tig) a2=(gid,k=tig+4) a3=(gid+8,k=tig+4)
                // V rows permuted so k=tig <-> col 2tig, k=tig+4 <-> col 2tig+1.
                aP[jj][0] = cvt_tf32(e0);
                aP[jj][1] = cvt_tf32(e2);
                aP[jj][2] = cvt_tf32(e1);
                aP[jj][3] = cvt_tf32(e3);
            }
            // ---- O += P(:, tk-chunk) @ V(tk-chunk, :)  (tf32, 2 MMAs/j) ----
            #pragma unroll
            for (int j = 0; j < 16; j++) {
                const uint4 f = *(const uint4*)&vb[((tk * 16 + j) * 32 + lane) * 4];
                mma_tf32(o[j], aP[0], f.x, f.y);   // kv 0-7 of chunk
                mma_tf32(o[j], aP[1], f.z, f.w);   // kv 8-15 of chunk
            }
        }
    }

    // ---- epilogue ----
    lsum0 += __shfl_xor_sync(0xffffffffu, lsum0, 1);
    lsum0 += __shfl_xor_sync(0xffffffffu, lsum0, 2);
    lsum1 += __shfl_xor_sync(0xffffffffu, lsum1, 1);
    lsum1 += __shfl_xor_sync(0xffffffffu, lsum1, 2);
    const float inv0 = 1.0f / lsum0, inv1 = 1.0f / lsum1;

    const int row0 = h * NQ_ + q0 + w * 16 + gid;
    #pragma unroll
    for (int j = 0; j < 16; j++) {
        const float2 v0 = make_float2(o[j][0] * inv0, o[j][1] * inv0);
        const float2 v1 = make_float2(o[j][2] * inv1, o[j][3] * inv1);
        *(float2*)(Og + (size_t)row0 * 128 + j * 8 + tig * 2) = v0;
        *(float2*)(Og + (size_t)(row0 + 8) * 128 + j * 8 + tig * 2) = v1;
    }
}

// ---------------- launch ----------------
extern "C" void kernel_launch(void* const* d_in, const int* in_sizes, int n_in,
                              void* d_out, int out_size)
{
    const float* Q = (const float*)d_in[0];
    const float* K = (const float*)d_in[1];
    const float* V = (const float*)d_in[2];
    const float* R = (const float*)d_in[3];
    float* O = (float*)d_out;

    uint32_t *qpk, *kpk, *vpk;
    cudaGetSymbolAddress((void**)&qpk, g_Qpk);
    cudaGetSymbolAddress((void**)&kpk, g_Kpk);
    cudaGetSymbolAddress((void**)&vpk, g_Vpk);

    cudaFuncSetAttribute(proj_pack<1>, cudaFuncAttributeMaxDynamicSharedMemorySize, PROJ_SMEM);
    cudaFuncSetAttribute(proj_pack<0>, cudaFuncAttributeMaxDynamicSharedMemorySize, PROJ_SMEM);
    cudaFuncSetAttribute(flash_mma, cudaFuncAttributeMaxDynamicSharedMemorySize, FLASH_SMEM);

    proj_pack<1><<<(H_ * NQ_) / 32, 256, PROJ_SMEM>>>(Q, R, qpk);
    proj_pack<0><<<(H_ * NKV_) / 32, 256, PROJ_SMEM>>>(K, R, kpk);
    vpack<<<H_ * 256, 256>>>(V, vpk);
    flash_mma<<<dim3(NQ_ / 128, H_), 256, FLASH_SMEM>>>(qpk, kpk, vpk, O);
}